// round 14
// baseline (speedup 1.0000x reference)
#include <cuda_runtime.h>
#include <cuda_bf16.h>
#include <cstdint>
#include <cmath>

#define NROWS 8192
#define XROWS 16384
#define DIM   64
#define BT    128                 // tile dim
#define NT    (XROWS / BT)        // 128 tiles per side
#define NTRI  (NT * (NT + 1) / 2) // 8256 upper-triangle tiles (column-major order)
#define LPAD  72                  // padded smem row stride (bf16 elems)
#define ROWB  (LPAD * 2)          // 144 bytes per smem row
#define TILEB (BT * ROWB)         // 18432 bytes per operand tile
#define RWOFF (4 * TILEB)         // rowsum offset: 73728 (2x Ls + 2x Rs buffers)
#define SMEM_TOTAL (RWOFF + BT * 4)   // 74240 bytes -> 3 CTAs/SM

#define SCALE_L2E 28.853900817779268f   // 20 * log2(e)

// ---------------- device scratch ----------------
__device__ __align__(16) __nv_bfloat16 g_Xs[XROWS * DIM];  // normalized * 20*log2(e)
__device__ __align__(16) __nv_bfloat16 g_Xn[XROWS * DIM];  // normalized
__device__ float g_part[XROWS];
__device__ float g_pos[NROWS];
__device__ int   g_done;

static __device__ __forceinline__ uint32_t smem_u32(const void* p) {
    uint32_t a;
    asm("{ .reg .u64 t; cvta.to.shared.u64 t, %1; cvt.u32.u64 %0, t; }" : "=r"(a) : "l"(p));
    return a;
}
static __device__ __forceinline__ float ex2f(float x) {
    float y; asm("ex2.approx.ftz.f32 %0, %1;" : "=f"(y) : "f"(x)); return y;
}
static __device__ __forceinline__ void cp16(uint32_t dst, const void* src) {
    asm volatile("cp.async.cg.shared.global [%0], [%1], 16;" :: "r"(dst), "l"(src) : "memory");
}
// column-major triangle: t = bj*(bj+1)/2 + bi, 0 <= bi <= bj
static __device__ __forceinline__ int col_of(int t) {
    int bj = (int)((sqrtf(8.0f * (float)t + 1.0f) - 1.0f) * 0.5f);
    if (bj < 0) bj = 0;
    if (bj > NT - 1) bj = NT - 1;
    while (bj * (bj + 1) / 2 > t) --bj;
    while ((bj + 1) * (bj + 2) / 2 <= t) ++bj;
    return bj;
}

// ---------------- kernel 1: normalize + bf16 + exact pos logit + zeroing (2 rows/warp) ----------------
__global__ void prep_kernel(const float* __restrict__ A, const float* __restrict__ P,
                            float* __restrict__ out) {
    int r0   = blockIdx.x * 16 + (threadIdx.x >> 5) * 2;
    int lane = threadIdx.x & 31;
    #pragma unroll
    for (int rr = 0; rr < 2; ++rr) {
        int row = r0 + rr;
        float a0 = A[(size_t)row * DIM + lane], a1 = A[(size_t)row * DIM + lane + 32];
        float p0 = P[(size_t)row * DIM + lane], p1 = P[(size_t)row * DIM + lane + 32];
        float sa = a0 * a0 + a1 * a1;
        float sp = p0 * p0 + p1 * p1;
        float d  = a0 * p0 + a1 * p1;
        #pragma unroll
        for (int o = 16; o; o >>= 1) {
            sa += __shfl_xor_sync(0xffffffffu, sa, o);
            sp += __shfl_xor_sync(0xffffffffu, sp, o);
            d  += __shfl_xor_sync(0xffffffffu, d,  o);
        }
        float ra = rsqrtf(fmaxf(sa, 1e-24f));
        float rp = rsqrtf(fmaxf(sp, 1e-24f));
        float va0 = a0 * ra, va1 = a1 * ra;
        float vp0 = p0 * rp, vp1 = p1 * rp;
        size_t ia = (size_t)row * DIM, ip = (size_t)(row + NROWS) * DIM;
        g_Xn[ia + lane]      = __float2bfloat16(va0);
        g_Xn[ia + lane + 32] = __float2bfloat16(va1);
        g_Xn[ip + lane]      = __float2bfloat16(vp0);
        g_Xn[ip + lane + 32] = __float2bfloat16(vp1);
        g_Xs[ia + lane]      = __float2bfloat16(va0 * SCALE_L2E);
        g_Xs[ia + lane + 32] = __float2bfloat16(va1 * SCALE_L2E);
        g_Xs[ip + lane]      = __float2bfloat16(vp0 * SCALE_L2E);
        g_Xs[ip + lane + 32] = __float2bfloat16(vp1 * SCALE_L2E);
        if (lane == 0) {
            g_pos[row] = 20.0f * d / fmaxf(sqrtf(sa) * sqrtf(sp), 1e-6f);
            g_part[row] = 0.0f;
            g_part[row + NROWS] = 0.0f;
        }
    }
    if (blockIdx.x == 0 && threadIdx.x == 0) { out[0] = 0.0f; g_done = 0; }
}

// ---------------- kernel 2: persistent column-major triangle GEMM (col-strip warps) ----------------
// Warp w owns cols [w*16, w*16+16); loops over 8 M-strips. B-frags reload only on
// column change; col partials live in 4 registers across the column; row partials
// staged per tile in rowsum[128] smem via atomics. 3 CTAs/SM. Diagonal tiles keep
// strict upper only (exactly replaces the -2*e^{1/T} self terms).
__global__ void __launch_bounds__(256, 3) mma_kernel(int Q, int R, int G,
                                                     float* __restrict__ out) {
    extern __shared__ __align__(16) unsigned char smem[];
    uint32_t sbase = smem_u32(smem);        // Ls buffers at 0, TILEB; Rs at 2*TILEB, 3*TILEB
    float* rowsum = (float*)(smem + RWOFF);

    int c = blockIdx.x;
    int t0 = c * Q + min(c, R);
    int t1 = t0 + Q + (c < R ? 1 : 0);

    int tid = threadIdx.x, wid = tid >> 5, lane = tid & 31;
    int gid = lane >> 2, tig = lane & 3;
    int b_u = (lane >> 4) & 1;
    int b_h = (lane >> 3) & 1;
    int b_r = lane & 7;

    if (tid < BT) rowsum[tid] = 0.0f;

    if (t0 < t1) {
        int bj = col_of(t0);
        int bi = t0 - bj * (bj + 1) / 2;
        int lbuf = 0, rbuf = 0;

        {   // prefetch first Ls + Rs
            const uint4* Lg = (const uint4*)(g_Xs + (size_t)bi * BT * DIM);
            const uint4* Rg = (const uint4*)(g_Xn + (size_t)bj * BT * DIM);
            #pragma unroll
            for (int it = 0; it < 4; ++it) {
                int f = tid + it * 256;
                uint32_t off = (uint32_t)(f >> 3) * ROWB + (uint32_t)(f & 7) * 16;
                cp16(sbase + off, Lg + f);
                cp16(sbase + 2 * TILEB + off, Rg + f);
            }
            asm volatile("cp.async.commit_group;" ::: "memory");
        }

        float cs[2][2] = {{0.f, 0.f}, {0.f, 0.f}};
        uint32_t bfr[2][4][2];
        bool bload = true;

        for (int t = t0; t < t1; ++t) {
            bool hasn = (t + 1 < t1);
            int bin = bi, bjn = bj;
            bool colchg = false;
            if (hasn) {
                if (bi < bj) { bin = bi + 1; }
                else         { bjn = bj + 1; bin = 0; colchg = true; }
                const uint4* Lg = (const uint4*)(g_Xs + (size_t)bin * BT * DIM);
                uint32_t lb = sbase + (uint32_t)(lbuf ^ 1) * TILEB;
                const uint4* Rg = (const uint4*)(g_Xn + (size_t)bjn * BT * DIM);
                uint32_t rb = sbase + (uint32_t)(2 + (rbuf ^ 1)) * TILEB;
                #pragma unroll
                for (int it = 0; it < 4; ++it) {
                    int f = tid + it * 256;
                    uint32_t off = (uint32_t)(f >> 3) * ROWB + (uint32_t)(f & 7) * 16;
                    cp16(lb + off, Lg + f);
                    if (colchg) cp16(rb + off, Rg + f);
                }
                asm volatile("cp.async.commit_group;" ::: "memory");
                asm volatile("cp.async.wait_group 1;" ::: "memory");
            } else {
                asm volatile("cp.async.wait_group 0;" ::: "memory");
            }
            __syncthreads();

            uint32_t Lbase = sbase + (uint32_t)lbuf * TILEB;
            uint32_t Rbase = sbase + (uint32_t)(2 + rbuf) * TILEB;

            if (bload) {   // B fragments for this warp's 16-col strip (whole column run)
                #pragma unroll
                for (int kc = 0; kc < 4; ++kc) {
                    uint32_t addr = Rbase + (uint32_t)(wid * 16 + b_u * 8 + b_r) * ROWB
                                  + (uint32_t)(kc * 16 + b_h * 8) * 2;
                    asm volatile("ldmatrix.sync.aligned.m8n8.x4.shared.b16 {%0,%1,%2,%3}, [%4];"
                                 : "=r"(bfr[0][kc][0]), "=r"(bfr[0][kc][1]),
                                   "=r"(bfr[1][kc][0]), "=r"(bfr[1][kc][1])
                                 : "r"(addr));
                }
                bload = false;
            }

            bool diag = (bi == bj);
            int grow0 = bi * BT;
            int mycol0 = bj * BT + wid * 16 + tig * 2;      // u=0 cols (pair)
            int mycol1 = mycol0 + 8;                         // u=1 cols (pair)

            #pragma unroll
            for (int mi = 0; mi < 8; ++mi) {
                uint32_t a[4][4];
                {
                    int r  = mi * 16 + (lane & 15);
                    int kh = (lane >> 4) * 8;
                    #pragma unroll
                    for (int kc = 0; kc < 4; ++kc) {
                        uint32_t addr = Lbase + (uint32_t)r * ROWB + (uint32_t)(kc * 16 + kh) * 2;
                        asm volatile("ldmatrix.sync.aligned.m8n8.x4.shared.b16 {%0,%1,%2,%3}, [%4];"
                                     : "=r"(a[kc][0]), "=r"(a[kc][1]), "=r"(a[kc][2]), "=r"(a[kc][3])
                                     : "r"(addr));
                    }
                }
                float c4[2][4] = {};
                #pragma unroll
                for (int kc = 0; kc < 4; ++kc) {
                    #pragma unroll
                    for (int u = 0; u < 2; ++u) {
                        asm volatile(
                            "mma.sync.aligned.m16n8k16.row.col.f32.bf16.bf16.f32 "
                            "{%0,%1,%2,%3}, {%4,%5,%6,%7}, {%8,%9}, {%0,%1,%2,%3};"
                            : "+f"(c4[u][0]), "+f"(c4[u][1]), "+f"(c4[u][2]), "+f"(c4[u][3])
                            : "r"(a[kc][0]), "r"(a[kc][1]), "r"(a[kc][2]), "r"(a[kc][3]),
                              "r"(bfr[u][kc][0]), "r"(bfr[u][kc][1]));
                    }
                }
                int r0 = grow0 + mi * 16 + gid;
                int r1 = r0 + 8;
                float row0s = 0.0f, row1s = 0.0f;
                #pragma unroll
                for (int u = 0; u < 2; ++u) {
                    float e0 = ex2f(c4[u][0]), e1 = ex2f(c4[u][1]);
                    float e2 = ex2f(c4[u][2]), e3 = ex2f(c4[u][3]);
                    if (diag) {   // strict upper triangle only
                        int col0 = u ? mycol1 : mycol0;
                        if (col0     <= r0) e0 = 0.0f;
                        if (col0 + 1 <= r0) e1 = 0.0f;
                        if (col0     <= r1) e2 = 0.0f;
                        if (col0 + 1 <= r1) e3 = 0.0f;
                    }
                    row0s += e0 + e1;
                    row1s += e2 + e3;
                    cs[u][0] += e0 + e2;
                    cs[u][1] += e1 + e3;
                }
                // reduce row partials over the 4 tig lanes, stage into smem
                row0s += __shfl_xor_sync(0xffffffffu, row0s, 1);
                row0s += __shfl_xor_sync(0xffffffffu, row0s, 2);
                row1s += __shfl_xor_sync(0xffffffffu, row1s, 1);
                row1s += __shfl_xor_sync(0xffffffffu, row1s, 2);
                if (tig == 0) {
                    atomicAdd(&rowsum[mi * 16 + gid], row0s);
                    atomicAdd(&rowsum[mi * 16 + gid + 8], row1s);
                }
            }

            __syncthreads();   // rowsum complete
            if (tid < BT) {
                atomicAdd(&g_part[grow0 + tid], rowsum[tid]);
                rowsum[tid] = 0.0f;
            }

            if (!hasn || colchg) {   // column ended: flush cs (12 shfl + 4 REDG)
                #pragma unroll
                for (int u = 0; u < 2; ++u) {
                    #pragma unroll
                    for (int p = 0; p < 2; ++p) {
                        float v = cs[u][p];
                        v += __shfl_xor_sync(0xffffffffu, v, 4);
                        v += __shfl_xor_sync(0xffffffffu, v, 8);
                        v += __shfl_xor_sync(0xffffffffu, v, 16);
                        if (gid == 0)
                            atomicAdd(&g_part[bj * BT + wid * 16 + u * 8 + tig * 2 + p], v);
                        cs[u][p] = 0.0f;
                    }
                }
                bload = true;
            }

            if (hasn) {
                lbuf ^= 1;
                if (colchg) rbuf ^= 1;
                bi = bin; bj = bjn;
            }
        }
    }

    // ---- fused loss: last CTA reduces g_part -> out[0] ----
    __shared__ int slast;
    __shared__ float wsum[8];
    __threadfence();
    if (tid == 0) slast = (atomicAdd(&g_done, 1) == G - 1) ? 1 : 0;
    __syncthreads();
    if (slast) {
        __threadfence();
        float s = 0.0f;
        for (int i = tid; i < NROWS; i += 256)
            s += __logf(g_part[i] + g_part[i + NROWS]) - g_pos[i];
        #pragma unroll
        for (int o = 16; o; o >>= 1) s += __shfl_xor_sync(0xffffffffu, s, o);
        if (lane == 0) wsum[wid] = s;
        __syncthreads();
        if (wid == 0) {
            float v = (lane < 8) ? wsum[lane] : 0.0f;
            #pragma unroll
            for (int o = 4; o; o >>= 1) v += __shfl_xor_sync(0xffffffffu, v, o);
            if (lane == 0) out[0] = v * (1.0f / (float)NROWS);
        }
    }
}

// ---------------- launch ----------------
extern "C" void kernel_launch(void* const* d_in, const int* in_sizes, int n_in,
                              void* d_out, int out_size) {
    const float* A = (const float*)d_in[0];
    const float* P = (const float*)d_in[1];
    int dev = 0, nsm = 148;
    cudaGetDevice(&dev);
    cudaDeviceGetAttribute(&nsm, cudaDevAttrMultiProcessorCount, dev);
    int G = nsm * 3;
    int Q = NTRI / G, R = NTRI % G;
    cudaFuncSetAttribute(mma_kernel, cudaFuncAttributeMaxDynamicSharedMemorySize, SMEM_TOTAL);
    prep_kernel<<<NROWS / 16, 256>>>(A, P, (float*)d_out);
    mma_kernel<<<G, 256, SMEM_TOTAL>>>(Q, R, G, (float*)d_out);
}

// round 15
// speedup vs baseline: 1.1576x; 1.1576x over previous
#include <cuda_runtime.h>
#include <cuda_bf16.h>
#include <cstdint>
#include <cmath>

#define NROWS 8192
#define XROWS 16384
#define DIM   64
#define BT    128                 // tile dim
#define NT    (XROWS / BT)        // 128 tiles per side
#define NTRI  (NT * (NT + 1) / 2) // 8256 upper-triangle tiles (column-major order)
#define LPAD  72                  // padded smem row stride (bf16 elems)
#define ROWB  (LPAD * 2)          // 144 bytes per smem row
#define TILEB (BT * ROWB)         // 18432 bytes per operand tile
#define SMEM_TOTAL (4 * TILEB)    // 73728 bytes (2x Ls + 2x Rs) -> 3 CTAs/SM

#define SCALE_L2E 28.853900817779268f   // 20 * log2(e)

// ---------------- device scratch ----------------
__device__ __align__(16) __nv_bfloat16 g_Xs[XROWS * DIM];  // normalized * 20*log2(e)
__device__ __align__(16) __nv_bfloat16 g_Xn[XROWS * DIM];  // normalized
__device__ float g_part[XROWS];
__device__ float g_pos[NROWS];
__device__ int   g_done;

static __device__ __forceinline__ uint32_t smem_u32(const void* p) {
    uint32_t a;
    asm("{ .reg .u64 t; cvta.to.shared.u64 t, %1; cvt.u32.u64 %0, t; }" : "=r"(a) : "l"(p));
    return a;
}
static __device__ __forceinline__ float ex2f(float x) {
    float y; asm("ex2.approx.ftz.f32 %0, %1;" : "=f"(y) : "f"(x)); return y;
}
static __device__ __forceinline__ void cp16(uint32_t dst, const void* src) {
    asm volatile("cp.async.cg.shared.global [%0], [%1], 16;" :: "r"(dst), "l"(src) : "memory");
}
// column-major triangle: t = bj*(bj+1)/2 + bi, 0 <= bi <= bj
static __device__ __forceinline__ int col_of(int t) {
    int bj = (int)((sqrtf(8.0f * (float)t + 1.0f) - 1.0f) * 0.5f);
    if (bj < 0) bj = 0;
    if (bj > NT - 1) bj = NT - 1;
    while (bj * (bj + 1) / 2 > t) --bj;
    while ((bj + 1) * (bj + 2) / 2 <= t) ++bj;
    return bj;
}

// ---------------- kernel 1: normalize + bf16 + exact pos logit + zeroing (2 rows/warp) ----------------
__global__ void prep_kernel(const float* __restrict__ A, const float* __restrict__ P,
                            float* __restrict__ out) {
    int r0   = blockIdx.x * 16 + (threadIdx.x >> 5) * 2;
    int lane = threadIdx.x & 31;
    #pragma unroll
    for (int rr = 0; rr < 2; ++rr) {
        int row = r0 + rr;
        float a0 = A[(size_t)row * DIM + lane], a1 = A[(size_t)row * DIM + lane + 32];
        float p0 = P[(size_t)row * DIM + lane], p1 = P[(size_t)row * DIM + lane + 32];
        float sa = a0 * a0 + a1 * a1;
        float sp = p0 * p0 + p1 * p1;
        float d  = a0 * p0 + a1 * p1;
        #pragma unroll
        for (int o = 16; o; o >>= 1) {
            sa += __shfl_xor_sync(0xffffffffu, sa, o);
            sp += __shfl_xor_sync(0xffffffffu, sp, o);
            d  += __shfl_xor_sync(0xffffffffu, d,  o);
        }
        float ra = rsqrtf(fmaxf(sa, 1e-24f));
        float rp = rsqrtf(fmaxf(sp, 1e-24f));
        float va0 = a0 * ra, va1 = a1 * ra;
        float vp0 = p0 * rp, vp1 = p1 * rp;
        size_t ia = (size_t)row * DIM, ip = (size_t)(row + NROWS) * DIM;
        g_Xn[ia + lane]      = __float2bfloat16(va0);
        g_Xn[ia + lane + 32] = __float2bfloat16(va1);
        g_Xn[ip + lane]      = __float2bfloat16(vp0);
        g_Xn[ip + lane + 32] = __float2bfloat16(vp1);
        g_Xs[ia + lane]      = __float2bfloat16(va0 * SCALE_L2E);
        g_Xs[ia + lane + 32] = __float2bfloat16(va1 * SCALE_L2E);
        g_Xs[ip + lane]      = __float2bfloat16(vp0 * SCALE_L2E);
        g_Xs[ip + lane + 32] = __float2bfloat16(vp1 * SCALE_L2E);
        if (lane == 0) {
            g_pos[row] = 20.0f * d / fmaxf(sqrtf(sa) * sqrtf(sp), 1e-6f);
            g_part[row] = 0.0f;
            g_part[row + NROWS] = 0.0f;
        }
    }
    if (blockIdx.x == 0 && threadIdx.x == 0) { out[0] = 0.0f; g_done = 0; }
}

// ---------------- kernel 2: persistent column-major triangle GEMM, 3 CTAs/SM ----------------
// R13 mainloop verbatim. Col partials in registers across the column; flushed
// via shfl-tree + global atomics ONCE per column run (amortized ~5 shfl/tile).
// No colpart smem -> 72KB smem -> 3 CTAs/SM. Diagonal tiles strict-upper only
// (exactly replaces the -2*e^{1/T} self terms). Last CTA reduces the loss.
__global__ void __launch_bounds__(256, 3) mma_kernel(int Q, int R, int G,
                                                     float* __restrict__ out) {
    extern __shared__ __align__(16) unsigned char smem[];
    uint32_t sbase = smem_u32(smem);        // Ls buffers at 0, TILEB; Rs at 2*TILEB, 3*TILEB

    int c = blockIdx.x;
    int t0 = c * Q + min(c, R);
    int t1 = t0 + Q + (c < R ? 1 : 0);

    int tid = threadIdx.x, wid = tid >> 5, lane = tid & 31;
    int gid = lane >> 2, tig = lane & 3;
    int b_u = (lane >> 4) & 1;
    int b_h = (lane >> 3) & 1;
    int b_r = lane & 7;

    if (t0 < t1) {
        int bj = col_of(t0);
        int bi = t0 - bj * (bj + 1) / 2;
        int lbuf = 0, rbuf = 0;

        {   // prefetch first Ls + Rs
            const uint4* Lg = (const uint4*)(g_Xs + (size_t)bi * BT * DIM);
            const uint4* Rg = (const uint4*)(g_Xn + (size_t)bj * BT * DIM);
            #pragma unroll
            for (int it = 0; it < 4; ++it) {
                int f = tid + it * 256;
                uint32_t off = (uint32_t)(f >> 3) * ROWB + (uint32_t)(f & 7) * 16;
                cp16(sbase + off, Lg + f);
                cp16(sbase + 2 * TILEB + off, Rg + f);
            }
            asm volatile("cp.async.commit_group;" ::: "memory");
        }

        float cs[16][2];
        #pragma unroll
        for (int i = 0; i < 16; ++i) { cs[i][0] = 0.0f; cs[i][1] = 0.0f; }

        for (int t = t0; t < t1; ++t) {
            bool hasn = (t + 1 < t1);
            int bin = bi, bjn = bj;
            bool colchg = false;
            if (hasn) {
                if (bi < bj) { bin = bi + 1; }
                else         { bjn = bj + 1; bin = 0; colchg = true; }
                const uint4* Lg = (const uint4*)(g_Xs + (size_t)bin * BT * DIM);
                uint32_t lb = sbase + (uint32_t)(lbuf ^ 1) * TILEB;
                const uint4* Rg = (const uint4*)(g_Xn + (size_t)bjn * BT * DIM);
                uint32_t rb = sbase + (uint32_t)(2 + (rbuf ^ 1)) * TILEB;
                #pragma unroll
                for (int it = 0; it < 4; ++it) {
                    int f = tid + it * 256;
                    uint32_t off = (uint32_t)(f >> 3) * ROWB + (uint32_t)(f & 7) * 16;
                    cp16(lb + off, Lg + f);
                    if (colchg) cp16(rb + off, Rg + f);
                }
                asm volatile("cp.async.commit_group;" ::: "memory");
                asm volatile("cp.async.wait_group 1;" ::: "memory");
            } else {
                asm volatile("cp.async.wait_group 0;" ::: "memory");
            }
            __syncthreads();

            uint32_t Lbase = sbase + (uint32_t)lbuf * TILEB;
            uint32_t Rbase = sbase + (uint32_t)(2 + rbuf) * TILEB;
            bool diag = (bi == bj);
            int grow0 = bi * BT, gcol0 = bj * BT;

            uint32_t a[4][4];
            {
                int r  = wid * 16 + (lane & 15);
                int kh = (lane >> 4) * 8;
                #pragma unroll
                for (int kc = 0; kc < 4; ++kc) {
                    uint32_t addr = Lbase + (uint32_t)r * ROWB + (uint32_t)(kc * 16 + kh) * 2;
                    asm volatile("ldmatrix.sync.aligned.m8n8.x4.shared.b16 {%0,%1,%2,%3}, [%4];"
                                 : "=r"(a[kc][0]), "=r"(a[kc][1]), "=r"(a[kc][2]), "=r"(a[kc][3])
                                 : "r"(addr));
                }
            }

            int myrow0 = grow0 + wid * 16 + gid;
            int myrow1 = myrow0 + 8;
            float row0s = 0.0f, row1s = 0.0f;

            #pragma unroll
            for (int n2 = 0; n2 < 8; ++n2) {
                uint32_t b[2][4][2];
                #pragma unroll
                for (int kc = 0; kc < 4; ++kc) {
                    uint32_t addr = Rbase + (uint32_t)(n2 * 16 + b_u * 8 + b_r) * ROWB
                                  + (uint32_t)(kc * 16 + b_h * 8) * 2;
                    asm volatile("ldmatrix.sync.aligned.m8n8.x4.shared.b16 {%0,%1,%2,%3}, [%4];"
                                 : "=r"(b[0][kc][0]), "=r"(b[0][kc][1]),
                                   "=r"(b[1][kc][0]), "=r"(b[1][kc][1])
                                 : "r"(addr));
                }
                float c4[2][4] = {};
                #pragma unroll
                for (int kc = 0; kc < 4; ++kc) {
                    #pragma unroll
                    for (int u = 0; u < 2; ++u) {
                        asm volatile(
                            "mma.sync.aligned.m16n8k16.row.col.f32.bf16.bf16.f32 "
                            "{%0,%1,%2,%3}, {%4,%5,%6,%7}, {%8,%9}, {%0,%1,%2,%3};"
                            : "+f"(c4[u][0]), "+f"(c4[u][1]), "+f"(c4[u][2]), "+f"(c4[u][3])
                            : "r"(a[kc][0]), "r"(a[kc][1]), "r"(a[kc][2]), "r"(a[kc][3]),
                              "r"(b[u][kc][0]), "r"(b[u][kc][1]));
                    }
                }
                #pragma unroll
                for (int u = 0; u < 2; ++u) {
                    float e0 = ex2f(c4[u][0]), e1 = ex2f(c4[u][1]);
                    float e2 = ex2f(c4[u][2]), e3 = ex2f(c4[u][3]);
                    if (diag) {   // strict upper triangle only (replaces -2*e^{1/T})
                        int gc0 = gcol0 + (n2 * 2 + u) * 8 + tig * 2;
                        if (gc0     <= myrow0) e0 = 0.0f;
                        if (gc0 + 1 <= myrow0) e1 = 0.0f;
                        if (gc0     <= myrow1) e2 = 0.0f;
                        if (gc0 + 1 <= myrow1) e3 = 0.0f;
                    }
                    row0s += e0 + e1;
                    row1s += e2 + e3;
                    int ci = n2 * 2 + u;
                    cs[ci][0] += e0 + e2;
                    cs[ci][1] += e1 + e3;
                }
            }

            // row flush: 4 shfl + 2 spread atomics
            #pragma unroll
            for (int o = 1; o < 4; o <<= 1) {
                row0s += __shfl_xor_sync(0xffffffffu, row0s, o);
                row1s += __shfl_xor_sync(0xffffffffu, row1s, o);
            }
            if (tig == 0) {
                atomicAdd(&g_part[myrow0], row0s);
                atomicAdd(&g_part[myrow1], row1s);
            }

            // col flush once per column run: shfl tree over gid lanes + atomics
            if (!hasn || colchg) {
                #pragma unroll
                for (int ci = 0; ci < 16; ++ci) {
                    #pragma unroll
                    for (int p = 0; p < 2; ++p) {
                        float v = cs[ci][p];
                        v += __shfl_xor_sync(0xffffffffu, v, 4);
                        v += __shfl_xor_sync(0xffffffffu, v, 8);
                        v += __shfl_xor_sync(0xffffffffu, v, 16);
                        if (gid == 0)
                            atomicAdd(&g_part[gcol0 + ci * 8 + tig * 2 + p], v);
                        cs[ci][p] = 0.0f;
                    }
                }
            }

            if (hasn) {
                lbuf ^= 1;
                if (colchg) rbuf ^= 1;
                bi = bin; bj = bjn;
            }
        }
    }

    // ---- fused loss: last CTA reduces g_part -> out[0] ----
    __shared__ int slast;
    __shared__ float wsum[8];
    __threadfence();
    if (tid == 0) slast = (atomicAdd(&g_done, 1) == G - 1) ? 1 : 0;
    __syncthreads();
    if (slast) {
        __threadfence();
        float s = 0.0f;
        for (int i = tid; i < NROWS; i += 256)
            s += __logf(g_part[i] + g_part[i + NROWS]) - g_pos[i];
        #pragma unroll
        for (int o = 16; o; o >>= 1) s += __shfl_xor_sync(0xffffffffu, s, o);
        if (lane == 0) wsum[wid] = s;
        __syncthreads();
        if (wid == 0) {
            float v = (lane < 8) ? wsum[lane] : 0.0f;
            #pragma unroll
            for (int o = 4; o; o >>= 1) v += __shfl_xor_sync(0xffffffffu, v, o);
            if (lane == 0) out[0] = v * (1.0f / (float)NROWS);
        }
    }
}

// ---------------- launch ----------------
extern "C" void kernel_launch(void* const* d_in, const int* in_sizes, int n_in,
                              void* d_out, int out_size) {
    const float* A = (const float*)d_in[0];
    const float* P = (const float*)d_in[1];
    int dev = 0, nsm = 148;
    cudaGetDevice(&dev);
    cudaDeviceGetAttribute(&nsm, cudaDevAttrMultiProcessorCount, dev);
    int G = nsm * 3;
    int Q = NTRI / G, R = NTRI % G;
    cudaFuncSetAttribute(mma_kernel, cudaFuncAttributeMaxDynamicSharedMemorySize, SMEM_TOTAL);
    prep_kernel<<<NROWS / 16, 256>>>(A, P, (float*)d_out);
    mma_kernel<<<G, 256, SMEM_TOTAL>>>(Q, R, G, (float*)d_out);
}

// round 16
// speedup vs baseline: 1.1690x; 1.0099x over previous
#include <cuda_runtime.h>
#include <cuda_bf16.h>
#include <cstdint>
#include <cmath>

#define NROWS 8192
#define XROWS 16384
#define DIM   64
#define BM    256                 // supertile rows
#define BN    128                 // supertile cols
#define NBJ   (XROWS / BN)        // 128 column tiles
#define NSUP  4160                // sum_{bj} (bj/2 + 1) column-major supertiles
#define LPAD  72                  // padded smem row stride (bf16 elems)
#define ROWB  (LPAD * 2)          // 144 bytes per smem row
#define LTILEB (BM * ROWB)        // 36864 bytes per Ls tile
#define RTILEB (BN * ROWB)        // 18432 bytes per Rs tile
#define RSOFF (2 * LTILEB)        // Rs buffers offset
#define SMEM_TOTAL (2 * LTILEB + 2 * RTILEB)   // 110592 bytes -> 2 CTAs/SM

#define SCALE_L2E 28.853900817779268f   // 20 * log2(e)

// ---------------- device scratch ----------------
__device__ __align__(16) __nv_bfloat16 g_Xs[XROWS * DIM];  // normalized * 20*log2(e)
__device__ __align__(16) __nv_bfloat16 g_Xn[XROWS * DIM];  // normalized
__device__ float g_part[XROWS];
__device__ float g_pos[NROWS];
__device__ int   g_done;

static __device__ __forceinline__ uint32_t smem_u32(const void* p) {
    uint32_t a;
    asm("{ .reg .u64 t; cvta.to.shared.u64 t, %1; cvt.u32.u64 %0, t; }" : "=r"(a) : "l"(p));
    return a;
}
static __device__ __forceinline__ float ex2f(float x) {
    float y; asm("ex2.approx.ftz.f32 %0, %1;" : "=f"(y) : "f"(x)); return y;
}
static __device__ __forceinline__ void cp16(uint32_t dst, const void* src) {
    asm volatile("cp.async.cg.shared.global [%0], [%1], 16;" :: "r"(dst), "l"(src) : "memory");
}
// tiles before column bj: F(bj) = bj + q*(q-1) for even bj=2q, bj + q*q for odd bj=2q+1
static __device__ __forceinline__ int tiles_before(int bj) {
    int q = bj >> 1;
    return bj + ((bj & 1) ? q * q : q * (q - 1));
}
static __device__ __forceinline__ int col_of(int t) {
    int bj = 2 * (int)sqrtf((float)t);
    if (bj > NBJ - 1) bj = NBJ - 1;
    if (bj < 0) bj = 0;
    while (tiles_before(bj) > t) --bj;
    while (bj < NBJ - 1 && tiles_before(bj + 1) <= t) ++bj;
    return bj;
}

// ---------------- kernel 1: normalize + bf16 + exact pos logit + zeroing (2 rows/warp) ----------------
__global__ void prep_kernel(const float* __restrict__ A, const float* __restrict__ P,
                            float* __restrict__ out) {
    int r0   = blockIdx.x * 16 + (threadIdx.x >> 5) * 2;
    int lane = threadIdx.x & 31;
    #pragma unroll
    for (int rr = 0; rr < 2; ++rr) {
        int row = r0 + rr;
        float a0 = A[(size_t)row * DIM + lane], a1 = A[(size_t)row * DIM + lane + 32];
        float p0 = P[(size_t)row * DIM + lane], p1 = P[(size_t)row * DIM + lane + 32];
        float sa = a0 * a0 + a1 * a1;
        float sp = p0 * p0 + p1 * p1;
        float d  = a0 * p0 + a1 * p1;
        #pragma unroll
        for (int o = 16; o; o >>= 1) {
            sa += __shfl_xor_sync(0xffffffffu, sa, o);
            sp += __shfl_xor_sync(0xffffffffu, sp, o);
            d  += __shfl_xor_sync(0xffffffffu, d,  o);
        }
        float ra = rsqrtf(fmaxf(sa, 1e-24f));
        float rp = rsqrtf(fmaxf(sp, 1e-24f));
        float va0 = a0 * ra, va1 = a1 * ra;
        float vp0 = p0 * rp, vp1 = p1 * rp;
        size_t ia = (size_t)row * DIM, ip = (size_t)(row + NROWS) * DIM;
        g_Xn[ia + lane]      = __float2bfloat16(va0);
        g_Xn[ia + lane + 32] = __float2bfloat16(va1);
        g_Xn[ip + lane]      = __float2bfloat16(vp0);
        g_Xn[ip + lane + 32] = __float2bfloat16(vp1);
        g_Xs[ia + lane]      = __float2bfloat16(va0 * SCALE_L2E);
        g_Xs[ia + lane + 32] = __float2bfloat16(va1 * SCALE_L2E);
        g_Xs[ip + lane]      = __float2bfloat16(vp0 * SCALE_L2E);
        g_Xs[ip + lane + 32] = __float2bfloat16(vp1 * SCALE_L2E);
        if (lane == 0) {
            g_pos[row] = 20.0f * d / fmaxf(sqrtf(sa) * sqrtf(sp), 1e-6f);
            g_part[row] = 0.0f;
            g_part[row + NROWS] = 0.0f;
        }
    }
    if (blockIdx.x == 0 && threadIdx.x == 0) { out[0] = 0.0f; g_done = 0; }
}

// ---------------- kernel 2: persistent column-major 256x128 supertile GEMM ----------------
// Column bj has floor(bj/2)+1 row-blocks (bi). Warp owns a 32-row strip x all 128
// cols: each b-load feeds 4 independent HMMA chains; B smem traffic per output
// halved vs 128x128 tiles. Rs resident per column; col partials in registers,
// flushed once per column run. Diagonal-crossing blocks (bi == bj/2) masked
// elementwise to the strict upper triangle (replaces -2*e^{1/T} exactly).
__global__ void __launch_bounds__(256, 2) mma_kernel(int Q, int R, int G,
                                                     float* __restrict__ out) {
    extern __shared__ __align__(16) unsigned char smem[];
    uint32_t sbase = smem_u32(smem);   // Ls buffers at 0, LTILEB; Rs at RSOFF, RSOFF+RTILEB

    int c = blockIdx.x;
    int t0 = c * Q + min(c, R);
    int t1 = t0 + Q + (c < R ? 1 : 0);

    int tid = threadIdx.x, wid = tid >> 5, lane = tid & 31;
    int gid = lane >> 2, tig = lane & 3;
    int b_u = (lane >> 4) & 1;
    int b_h = (lane >> 3) & 1;
    int b_r = lane & 7;

    if (t0 < t1) {
        int bj = col_of(t0);
        int bi = t0 - tiles_before(bj);
        int lbuf = 0, rbuf = 0;

        {   // prefetch first Ls (2048 chunks) + Rs (1024 chunks)
            const uint4* Lg = (const uint4*)(g_Xs + (size_t)bi * BM * DIM);
            const uint4* Rg = (const uint4*)(g_Xn + (size_t)bj * BN * DIM);
            #pragma unroll
            for (int it = 0; it < 8; ++it) {
                int f = tid + it * 256;
                cp16(sbase + (uint32_t)(f >> 3) * ROWB + (uint32_t)(f & 7) * 16, Lg + f);
            }
            #pragma unroll
            for (int it = 0; it < 4; ++it) {
                int f = tid + it * 256;
                cp16(sbase + RSOFF + (uint32_t)(f >> 3) * ROWB + (uint32_t)(f & 7) * 16, Rg + f);
            }
            asm volatile("cp.async.commit_group;" ::: "memory");
        }

        float cs[16][2];
        #pragma unroll
        for (int i = 0; i < 16; ++i) { cs[i][0] = 0.0f; cs[i][1] = 0.0f; }

        for (int t = t0; t < t1; ++t) {
            bool hasn = (t + 1 < t1);
            int bin = bi, bjn = bj;
            bool colchg = false;
            if (hasn) {
                if (bi < (bj >> 1)) { bin = bi + 1; }
                else                { bjn = bj + 1; bin = 0; colchg = true; }
                const uint4* Lg = (const uint4*)(g_Xs + (size_t)bin * BM * DIM);
                uint32_t lb = sbase + (uint32_t)(lbuf ^ 1) * LTILEB;
                const uint4* Rg = (const uint4*)(g_Xn + (size_t)bjn * BN * DIM);
                uint32_t rb = sbase + RSOFF + (uint32_t)(rbuf ^ 1) * RTILEB;
                #pragma unroll
                for (int it = 0; it < 8; ++it) {
                    int f = tid + it * 256;
                    cp16(lb + (uint32_t)(f >> 3) * ROWB + (uint32_t)(f & 7) * 16, Lg + f);
                }
                if (colchg) {
                    #pragma unroll
                    for (int it = 0; it < 4; ++it) {
                        int f = tid + it * 256;
                        cp16(rb + (uint32_t)(f >> 3) * ROWB + (uint32_t)(f & 7) * 16, Rg + f);
                    }
                }
                asm volatile("cp.async.commit_group;" ::: "memory");
                asm volatile("cp.async.wait_group 1;" ::: "memory");
            } else {
                asm volatile("cp.async.wait_group 0;" ::: "memory");
            }
            __syncthreads();

            uint32_t Lbase = sbase + (uint32_t)lbuf * LTILEB;
            uint32_t Rbase = sbase + RSOFF + (uint32_t)rbuf * RTILEB;
            bool diag = (bi == (bj >> 1));
            int grow0 = bi * BM, gcol0 = bj * BN;

            // A fragments: warp's 32-row strip (2 m-halves), all of K=64
            uint32_t a[2][4][4];
            #pragma unroll
            for (int mh = 0; mh < 2; ++mh) {
                int r  = wid * 32 + mh * 16 + (lane & 15);
                int kh = (lane >> 4) * 8;
                #pragma unroll
                for (int kc = 0; kc < 4; ++kc) {
                    uint32_t addr = Lbase + (uint32_t)r * ROWB + (uint32_t)(kc * 16 + kh) * 2;
                    asm volatile("ldmatrix.sync.aligned.m8n8.x4.shared.b16 {%0,%1,%2,%3}, [%4];"
                                 : "=r"(a[mh][kc][0]), "=r"(a[mh][kc][1]),
                                   "=r"(a[mh][kc][2]), "=r"(a[mh][kc][3])
                                 : "r"(addr));
                }
            }

            int myrow0 = grow0 + wid * 32 + gid;       // mh0 rows (and +8)
            int myrow2 = myrow0 + 16;                  // mh1 rows (and +8)
            float rs[2][2] = {{0.f, 0.f}, {0.f, 0.f}}; // [mh][half]

            #pragma unroll
            for (int n2 = 0; n2 < 8; ++n2) {
                uint32_t b[2][4][2];
                #pragma unroll
                for (int kc = 0; kc < 4; ++kc) {
                    uint32_t addr = Rbase + (uint32_t)(n2 * 16 + b_u * 8 + b_r) * ROWB
                                  + (uint32_t)(kc * 16 + b_h * 8) * 2;
                    asm volatile("ldmatrix.sync.aligned.m8n8.x4.shared.b16 {%0,%1,%2,%3}, [%4];"
                                 : "=r"(b[0][kc][0]), "=r"(b[0][kc][1]),
                                   "=r"(b[1][kc][0]), "=r"(b[1][kc][1])
                                 : "r"(addr));
                }
                float c4[2][2][4] = {};   // [mh][u][4] — 4 independent chains
                #pragma unroll
                for (int kc = 0; kc < 4; ++kc) {
                    #pragma unroll
                    for (int mh = 0; mh < 2; ++mh) {
                        #pragma unroll
                        for (int u = 0; u < 2; ++u) {
                            asm volatile(
                                "mma.sync.aligned.m16n8k16.row.col.f32.bf16.bf16.f32 "
                                "{%0,%1,%2,%3}, {%4,%5,%6,%7}, {%8,%9}, {%0,%1,%2,%3};"
                                : "+f"(c4[mh][u][0]), "+f"(c4[mh][u][1]),
                                  "+f"(c4[mh][u][2]), "+f"(c4[mh][u][3])
                                : "r"(a[mh][kc][0]), "r"(a[mh][kc][1]),
                                  "r"(a[mh][kc][2]), "r"(a[mh][kc][3]),
                                  "r"(b[u][kc][0]), "r"(b[u][kc][1]));
                        }
                    }
                }
                #pragma unroll
                for (int mh = 0; mh < 2; ++mh) {
                    int r0 = mh ? myrow2 : myrow0;
                    #pragma unroll
                    for (int u = 0; u < 2; ++u) {
                        float e0 = ex2f(c4[mh][u][0]), e1 = ex2f(c4[mh][u][1]);
                        float e2 = ex2f(c4[mh][u][2]), e3 = ex2f(c4[mh][u][3]);
                        if (diag) {   // strict upper triangle only
                            int gc0 = gcol0 + (n2 * 2 + u) * 8 + tig * 2;
                            if (gc0     <= r0)     e0 = 0.0f;
                            if (gc0 + 1 <= r0)     e1 = 0.0f;
                            if (gc0     <= r0 + 8) e2 = 0.0f;
                            if (gc0 + 1 <= r0 + 8) e3 = 0.0f;
                        }
                        rs[mh][0] += e0 + e1;
                        rs[mh][1] += e2 + e3;
                        int ci = n2 * 2 + u;
                        cs[ci][0] += e0 + e2;
                        cs[ci][1] += e1 + e3;
                    }
                }
            }

            // row flush: 8 shfl + 4 spread atomics
            #pragma unroll
            for (int mh = 0; mh < 2; ++mh) {
                #pragma unroll
                for (int h = 0; h < 2; ++h) {
                    float v = rs[mh][h];
                    v += __shfl_xor_sync(0xffffffffu, v, 1);
                    v += __shfl_xor_sync(0xffffffffu, v, 2);
                    if (tig == 0)
                        atomicAdd(&g_part[(mh ? myrow2 : myrow0) + h * 8], v);
                }
            }

            // col flush once per column run: shfl tree over gid lanes + atomics
            if (!hasn || colchg) {
                #pragma unroll
                for (int ci = 0; ci < 16; ++ci) {
                    #pragma unroll
                    for (int p = 0; p < 2; ++p) {
                        float v = cs[ci][p];
                        v += __shfl_xor_sync(0xffffffffu, v, 4);
                        v += __shfl_xor_sync(0xffffffffu, v, 8);
                        v += __shfl_xor_sync(0xffffffffu, v, 16);
                        if (gid == 0)
                            atomicAdd(&g_part[gcol0 + ci * 8 + tig * 2 + p], v);
                        cs[ci][p] = 0.0f;
                    }
                }
            }

            if (hasn) {
                lbuf ^= 1;
                if (colchg) rbuf ^= 1;
                bi = bin; bj = bjn;
            }
        }
    }

    // ---- fused loss: last CTA reduces g_part -> out[0] ----
    __shared__ int slast;
    __shared__ float wsum[8];
    __threadfence();
    if (tid == 0) slast = (atomicAdd(&g_done, 1) == G - 1) ? 1 : 0;
    __syncthreads();
    if (slast) {
        __threadfence();
        float s = 0.0f;
        for (int i = tid; i < NROWS; i += 256)
            s += __logf(g_part[i] + g_part[i + NROWS]) - g_pos[i];
        #pragma unroll
        for (int o = 16; o; o >>= 1) s += __shfl_xor_sync(0xffffffffu, s, o);
        if (lane == 0) wsum[wid] = s;
        __syncthreads();
        if (wid == 0) {
            float v = (lane < 8) ? wsum[lane] : 0.0f;
            #pragma unroll
            for (int o = 4; o; o >>= 1) v += __shfl_xor_sync(0xffffffffu, v, o);
            if (lane == 0) out[0] = v * (1.0f / (float)NROWS);
        }
    }
}

// ---------------- launch ----------------
extern "C" void kernel_launch(void* const* d_in, const int* in_sizes, int n_in,
                              void* d_out, int out_size) {
    const float* A = (const float*)d_in[0];
    const float* P = (const float*)d_in[1];
    int dev = 0, nsm = 148;
    cudaGetDevice(&dev);
    cudaDeviceGetAttribute(&nsm, cudaDevAttrMultiProcessorCount, dev);
    int G = nsm * 2;
    int Q = NSUP / G, R = NSUP % G;
    cudaFuncSetAttribute(mma_kernel, cudaFuncAttributeMaxDynamicSharedMemorySize, SMEM_TOTAL);
    prep_kernel<<<NROWS / 16, 256>>>(A, P, (float*)d_out);
    mma_kernel<<<G, 256, SMEM_TOTAL>>>(Q, R, G, (float*)d_out);
}